// round 15
// baseline (speedup 1.0000x reference)
#include <cuda_runtime.h>
#include <cuda_fp16.h>
#include <cstddef>

#define DIM 128
#define MAX_USERS 100000
#define MAX_ITEMS 50000
#define MAX_NT   (MAX_USERS + MAX_ITEMS)
#define NNZ_U   3200000
#define NNZ_I   1600000
#define NNZ_TOT (3 * NNZ_U + 3 * NNZ_I)
#define CNT_L   (3 * (MAX_USERS + 1) + 3 * (MAX_ITEMS + 1))
#define SCAN_T  1024
#define MAX_SCAN_BLOCKS 512

#define STAGE_SCALE 0.25f

// ---- persistent scratch ----
__device__ __half g_E [(size_t)MAX_NT * DIM];   // fp16 embeddings (both branches)
__device__ __half g_T [(size_t)MAX_NT * DIM];
__device__ __half g_S [(size_t)MAX_NT * DIM];
__device__ __half g_H1[(size_t)MAX_NT * DIM];
__device__ __half g_H2[(size_t)MAX_NT * DIM];

__device__ int2 g_edges[NNZ_TOT];   // packed (col_byte_offset, val_bits)
__device__ int  g_counts[CNT_L];    // zeroed by scan kernel each call
__device__ int  g_offs  [CNT_L];
__device__ int  g_cur   [CNT_L];

// decoupled-lookback scan state (zeroed by scatter kernel each call; load-time zero)
__device__ unsigned long long g_desc[MAX_SCAN_BLOCKS];
__device__ int g_scan_ctr;

#define FLAG_AGG 1ULL
#define FLAG_PRE 2ULL

struct BuildArgs {
    const int*   rows[6];
    const int*   cols[6];
    const float* vals[6];
    int ebase[7];
    int cbase[7];
};

// ---------------- kernel 1: embedding convert + unified histogram ----------------
__global__ void convhist_kernel(BuildArgs a, int* __restrict__ counts,
                                const float* __restrict__ ue,
                                const float* __restrict__ ie,
                                __half* __restrict__ E,
                                size_t u4, size_t n4, int total) {
    size_t i = (size_t)blockIdx.x * blockDim.x + threadIdx.x;

    if (i < n4) {
        float4 x = (i < u4) ? __ldg(reinterpret_cast<const float4*>(ue) + i)
                            : __ldg(reinterpret_cast<const float4*>(ie) + (i - u4));
        __half2 p0 = __floats2half2_rn(x.x, x.y);
        __half2 p1 = __floats2half2_rn(x.z, x.w);
        uint2 o;
        o.x = *reinterpret_cast<unsigned*>(&p0);
        o.y = *reinterpret_cast<unsigned*>(&p1);
        reinterpret_cast<uint2*>(E)[i] = o;
    }

    if (i < (size_t)total) {
        int k = 0;
        #pragma unroll
        for (int j = 1; j < 6; j++) if ((int)i >= a.ebase[j]) k = j;
        int local = (int)i - a.ebase[k];
        int r = __ldg(a.rows[k] + local);
        atomicAdd(&counts[a.cbase[k] + r + 1], 1);
    }
}

// ---------------- kernel 2: single-pass inclusive scan (decoupled lookback) ----
__global__ void scan_lookback_kernel(int* __restrict__ counts,
                                     int* __restrict__ offs,
                                     int* __restrict__ cur, int m) {
    __shared__ int sh[SCAN_T];
    __shared__ int sbid;
    __shared__ int sprefix;

    if (threadIdx.x == 0) sbid = atomicAdd(&g_scan_ctr, 1);
    __syncthreads();
    int bid = sbid;

    int i = bid * SCAN_T + threadIdx.x;
    int x = (i < m) ? counts[i] : 0;
    if (i < m) counts[i] = 0;          // reset for next call's histogram

    sh[threadIdx.x] = x;
    __syncthreads();
    for (int off = 1; off < SCAN_T; off <<= 1) {
        int t = (threadIdx.x >= off) ? sh[threadIdx.x - off] : 0;
        __syncthreads();
        sh[threadIdx.x] += t;
        __syncthreads();
    }
    int agg = sh[SCAN_T - 1];

    if (threadIdx.x == 0) {
        if (bid == 0) {
            atomicExch(&g_desc[0], (FLAG_PRE << 32) | (unsigned long long)(unsigned)agg);
            sprefix = 0;
        } else {
            atomicExch(&g_desc[bid], (FLAG_AGG << 32) | (unsigned long long)(unsigned)agg);
            int excl = 0;
            int j = bid - 1;
            while (true) {
                unsigned long long d = atomicAdd(&g_desc[j], 0ULL);
                unsigned long long flag = d >> 32;
                int val = (int)(unsigned)(d & 0xffffffffULL);
                if (flag == FLAG_PRE) { excl += val; break; }
                if (flag == FLAG_AGG) { excl += val; j--; }
            }
            atomicExch(&g_desc[bid],
                       (FLAG_PRE << 32) | (unsigned long long)(unsigned)(excl + agg));
            sprefix = excl;
        }
    }
    __syncthreads();

    if (i < m) {
        int v = sh[threadIdx.x] + sprefix;
        offs[i] = v;
        cur[i]  = v;
    }
}

// ---------------- kernel 3: scatter (pre-scales col to byte offset) ----------
__global__ void scatter_all_kernel(BuildArgs a, int* __restrict__ cur,
                                   int2* __restrict__ edges, int total,
                                   int n_users) {
    int i = blockIdx.x * blockDim.x + threadIdx.x;

    if (blockIdx.x == 0 && threadIdx.x < MAX_SCAN_BLOCKS)
        g_desc[threadIdx.x] = 0ULL;
    if (i == 0) g_scan_ctr = 0;

    if (i >= total) return;
    int k = 0;
    #pragma unroll
    for (int j = 1; j < 6; j++) if (i >= a.ebase[j]) k = j;
    int local = i - a.ebase[k];
    int r = __ldg(a.rows[k] + local);
    int p = atomicAdd(&cur[a.cbase[k] + r], 1);
    int colb = (k < 3) ? 0 : n_users;                 // item cols live after users
    int col  = __ldg(a.cols[k] + local);
    edges[p] = make_int2((colb + col) * (DIM * 2),    // byte offset into fp16 h
                         __float_as_int(__ldg(a.vals[k] + local)));
}

// ---------------- core gather loop: EXACT R11 structure (frozen) --------------
// Only change vs R11: edges loaded with __ldcs (streaming, evict-first) so the
// once-read edge stream does not evict the heavily reused h tiles from L1.
__device__ __forceinline__ float4 gather_row(const int* __restrict__ offs_row,
                                             const int2* __restrict__ edges,
                                             const char* __restrict__ hp) {
    int beg = __ldg(offs_row);
    int end = __ldg(offs_row + 1);
    float4 acc = make_float4(0.f, 0.f, 0.f, 0.f);
    #pragma unroll 4
    for (int e = beg; e < end; e++) {
        int2 ed = __ldcs(edges + e);                      // streaming broadcast
        float v = __int_as_float(ed.y);
        uint2 u = __ldg(reinterpret_cast<const uint2*>(hp + ed.x));
        float2 lo = __half22float2(*reinterpret_cast<__half2*>(&u.x));
        float2 hi = __half22float2(*reinterpret_cast<__half2*>(&u.y));
        acc.x += v * lo.x;
        acc.y += v * lo.y;
        acc.z += v * hi.x;
        acc.w += v * hi.y;
    }
    return acc;
}

// ---------------- fused CSR SpMM (intermediate stages, fp16 out) ----------------
__global__ void spmm_fused_kernel(const int* __restrict__ offs_u,
                                  const int* __restrict__ offs_i,
                                  const int2* __restrict__ edges,
                                  const __half* __restrict__ h,
                                  __half* __restrict__ out,
                                  int n_users, int n_total) {
    int w = (blockIdx.x * blockDim.x + threadIdx.x) >> 5;
    if (w >= n_total) return;
    int lane = threadIdx.x & 31;

    const int* orow = (w < n_users) ? (offs_u + w) : (offs_i + (w - n_users));
    const char* hp = reinterpret_cast<const char*>(h) + lane * 8;

    float4 acc = gather_row(orow, edges, hp);

    __half2 p0 = __floats2half2_rn(acc.x * STAGE_SCALE, acc.y * STAGE_SCALE);
    __half2 p1 = __floats2half2_rn(acc.z * STAGE_SCALE, acc.w * STAGE_SCALE);
    uint2 o;
    o.x = *reinterpret_cast<unsigned*>(&p0);
    o.y = *reinterpret_cast<unsigned*>(&p1);
    reinterpret_cast<uint2*>(out)[(size_t)w * (DIM / 4) + lane] = o;
}

// ---------------- final stage: SpMM + layer mean fused ----------------
// out = 0.25 * (emb + 64*H1 + 4096*H2 + 65536*acc)
__global__ void spmm_final_kernel(const int* __restrict__ offs_u,
                                  const int* __restrict__ offs_i,
                                  const int2* __restrict__ edges,
                                  const __half* __restrict__ h,
                                  const float* __restrict__ ue,
                                  const float* __restrict__ ie,
                                  const __half* __restrict__ h1,
                                  const __half* __restrict__ h2,
                                  float* __restrict__ out,
                                  int n_users, int n_total) {
    int w = (blockIdx.x * blockDim.x + threadIdx.x) >> 5;
    if (w >= n_total) return;
    int lane = threadIdx.x & 31;

    const int* orow;
    const float* emb;
    if (w < n_users) { orow = offs_u + w;             emb = ue + (size_t)w * DIM; }
    else             { orow = offs_i + (w - n_users); emb = ie + (size_t)(w - n_users) * DIM; }
    const char* hp = reinterpret_cast<const char*>(h) + lane * 8;

    float4 acc = gather_row(orow, edges, hp);

    size_t ri = (size_t)w * (DIM / 4) + lane;
    float4 a = __ldg(reinterpret_cast<const float4*>(emb) + lane);
    uint2 ub = __ldg(reinterpret_cast<const uint2*>(h1) + ri);
    uint2 uc = __ldg(reinterpret_cast<const uint2*>(h2) + ri);
    float2 b0 = __half22float2(*reinterpret_cast<__half2*>(&ub.x));
    float2 b1 = __half22float2(*reinterpret_cast<__half2*>(&ub.y));
    float2 c0 = __half22float2(*reinterpret_cast<__half2*>(&uc.x));
    float2 c1 = __half22float2(*reinterpret_cast<__half2*>(&uc.y));

    const float w1 = 64.0f, w2 = 4096.0f, w3 = 65536.0f;
    float4 o;
    o.x = 0.25f * (a.x + w1 * b0.x + w2 * c0.x + w3 * acc.x);
    o.y = 0.25f * (a.y + w1 * b0.y + w2 * c0.y + w3 * acc.y);
    o.z = 0.25f * (a.z + w1 * b1.x + w2 * c1.x + w3 * acc.z);
    o.w = 0.25f * (a.w + w1 * b1.y + w2 * c1.y + w3 * acc.w);
    reinterpret_cast<float4*>(out)[ri] = o;
}

static inline void launch_spmm(const int* offs_u, const int* offs_i, const int2* edges,
                               const __half* h, __half* out, int n_users, int n_total) {
    long long total = (long long)n_total * 32;
    int blocks = (int)((total + 255) / 256);
    spmm_fused_kernel<<<blocks, 256>>>(offs_u, offs_i, edges, h, out, n_users, n_total);
}

extern "C" void kernel_launch(void* const* d_in, const int* in_sizes, int n_in,
                              void* d_out, int out_size) {
    const float* user_emb = (const float*)d_in[0];
    const float* item_emb = (const float*)d_in[1];

    BuildArgs a;
    int mrows[6];
    int n_users = in_sizes[0] / DIM;
    int n_items = in_sizes[1] / DIM;
    mrows[0] = mrows[1] = mrows[2] = n_users;   // u1, u2, ucat
    mrows[3] = mrows[4] = mrows[5] = n_items;   // i1, i2, icat

    a.ebase[0] = 0;
    a.cbase[0] = 0;
    for (int k = 0; k < 6; k++) {
        a.rows[k] = (const int*)  d_in[2 + 3 * k];
        a.cols[k] = (const int*)  d_in[3 + 3 * k];
        a.vals[k] = (const float*)d_in[4 + 3 * k];
        a.ebase[k + 1] = a.ebase[k] + in_sizes[2 + 3 * k];
        a.cbase[k + 1] = a.cbase[k] + mrows[k] + 1;
    }
    int total_nnz = a.ebase[6];
    int L = a.cbase[6];
    int n_total = n_users + n_items;

    __half *E, *T, *S, *H1, *H2;
    cudaGetSymbolAddress((void**)&E,  g_E);
    cudaGetSymbolAddress((void**)&T,  g_T);
    cudaGetSymbolAddress((void**)&S,  g_S);
    cudaGetSymbolAddress((void**)&H1, g_H1);
    cudaGetSymbolAddress((void**)&H2, g_H2);

    int *counts, *offs, *cur; int2* edges;
    cudaGetSymbolAddress((void**)&counts, g_counts);
    cudaGetSymbolAddress((void**)&offs,   g_offs);
    cudaGetSymbolAddress((void**)&cur,    g_cur);
    cudaGetSymbolAddress((void**)&edges,  g_edges);

    size_t u4 = (size_t)n_users * (DIM / 4);
    size_t n4 = (size_t)n_total * (DIM / 4);

    // kernel 1: convert embeddings + histogram
    {
        size_t work = (size_t)total_nnz > n4 ? (size_t)total_nnz : n4;
        int blocks = (int)((work + 255) / 256);
        convhist_kernel<<<blocks, 256>>>(a, counts, user_emb, item_emb, E,
                                         u4, n4, total_nnz);
    }

    // kernel 2: single-pass scan (writes offs + cur, zeroes counts)
    {
        int nb = (L + SCAN_T - 1) / SCAN_T;
        scan_lookback_kernel<<<nb, SCAN_T>>>(counts, offs, cur, L);
    }

    // kernel 3: scatter into CSR edge slab (prescaled col byte offsets)
    scatter_all_kernel<<<(total_nnz + 255) / 256, 256>>>(a, cur, edges, total_nnz,
                                                         n_users);

    const int* O[6];
    for (int k = 0; k < 6; k++) O[k] = offs + a.cbase[k];

    // --- fused propagation: per layer, stage order m2, m1, mcat ---
    launch_spmm(O[1], O[4], edges, E, T,  n_users, n_total);
    launch_spmm(O[0], O[3], edges, T, S,  n_users, n_total);
    launch_spmm(O[2], O[5], edges, S, H1, n_users, n_total);

    launch_spmm(O[1], O[4], edges, H1, T, n_users, n_total);
    launch_spmm(O[0], O[3], edges, T,  S, n_users, n_total);
    launch_spmm(O[2], O[5], edges, S, H2, n_users, n_total);

    launch_spmm(O[1], O[4], edges, H2, T, n_users, n_total);
    launch_spmm(O[0], O[3], edges, T,  S, n_users, n_total);

    // final stage: SpMM(mcat, S) fused with the 4-layer mean -> d_out
    {
        long long total = (long long)n_total * 32;
        int blocks = (int)((total + 255) / 256);
        spmm_final_kernel<<<blocks, 256>>>(O[2], O[5], edges, S,
                                           user_emb, item_emb, H1, H2,
                                           (float*)d_out, n_users, n_total);
    }
}

// round 17
// speedup vs baseline: 1.0500x; 1.0500x over previous
#include <cuda_runtime.h>
#include <cuda_fp16.h>
#include <cstddef>

#define DIM 128
#define MAX_USERS 100000
#define MAX_ITEMS 50000
#define MAX_NT   (MAX_USERS + MAX_ITEMS)
#define NNZ_U   3200000
#define NNZ_I   1600000
#define NNZ_TOT (3 * NNZ_U + 3 * NNZ_I)
#define CNT_L   (3 * (MAX_USERS + 1) + 3 * (MAX_ITEMS + 1))
#define SCAN_T  1024
#define MAX_SCAN_BLOCKS 512

#define STAGE_SCALE 0.25f

// ---- persistent scratch ----
__device__ __half g_E [(size_t)MAX_NT * DIM];   // fp16 embeddings (both branches)
__device__ __half g_T [(size_t)MAX_NT * DIM];
__device__ __half g_S [(size_t)MAX_NT * DIM];
__device__ __half g_H1[(size_t)MAX_NT * DIM];
__device__ __half g_H2[(size_t)MAX_NT * DIM];

__device__ int2 g_edges[NNZ_TOT];   // packed (col_byte_offset, val_bits)
__device__ int  g_counts[CNT_L];    // zeroed by scan kernel each call
__device__ int  g_offs  [CNT_L];
__device__ int  g_cur   [CNT_L];

// decoupled-lookback scan state (zeroed by scatter kernel each call; load-time zero)
__device__ unsigned long long g_desc[MAX_SCAN_BLOCKS];
__device__ int g_scan_ctr;

#define FLAG_AGG 1ULL
#define FLAG_PRE 2ULL

struct BuildArgs {
    const int*   rows[6];
    const int*   cols[6];
    const float* vals[6];
    int ebase[7];
    int cbase[7];
};

// ---------------- kernel 1: embedding convert + unified histogram ----------------
__global__ void convhist_kernel(BuildArgs a, int* __restrict__ counts,
                                const float* __restrict__ ue,
                                const float* __restrict__ ie,
                                __half* __restrict__ E,
                                size_t u4, size_t n4, int total) {
    size_t i = (size_t)blockIdx.x * blockDim.x + threadIdx.x;

    if (i < n4) {
        float4 x = (i < u4) ? __ldg(reinterpret_cast<const float4*>(ue) + i)
                            : __ldg(reinterpret_cast<const float4*>(ie) + (i - u4));
        __half2 p0 = __floats2half2_rn(x.x, x.y);
        __half2 p1 = __floats2half2_rn(x.z, x.w);
        uint2 o;
        o.x = *reinterpret_cast<unsigned*>(&p0);
        o.y = *reinterpret_cast<unsigned*>(&p1);
        reinterpret_cast<uint2*>(E)[i] = o;
    }

    if (i < (size_t)total) {
        int k = 0;
        #pragma unroll
        for (int j = 1; j < 6; j++) if ((int)i >= a.ebase[j]) k = j;
        int local = (int)i - a.ebase[k];
        int r = __ldg(a.rows[k] + local);
        atomicAdd(&counts[a.cbase[k] + r + 1], 1);
    }
}

// ---------------- kernel 2: single-pass inclusive scan (decoupled lookback) ----
__global__ void scan_lookback_kernel(int* __restrict__ counts,
                                     int* __restrict__ offs,
                                     int* __restrict__ cur, int m) {
    __shared__ int sh[SCAN_T];
    __shared__ int sbid;
    __shared__ int sprefix;

    if (threadIdx.x == 0) sbid = atomicAdd(&g_scan_ctr, 1);
    __syncthreads();
    int bid = sbid;

    int i = bid * SCAN_T + threadIdx.x;
    int x = (i < m) ? counts[i] : 0;
    if (i < m) counts[i] = 0;          // reset for next call's histogram

    sh[threadIdx.x] = x;
    __syncthreads();
    for (int off = 1; off < SCAN_T; off <<= 1) {
        int t = (threadIdx.x >= off) ? sh[threadIdx.x - off] : 0;
        __syncthreads();
        sh[threadIdx.x] += t;
        __syncthreads();
    }
    int agg = sh[SCAN_T - 1];

    if (threadIdx.x == 0) {
        if (bid == 0) {
            atomicExch(&g_desc[0], (FLAG_PRE << 32) | (unsigned long long)(unsigned)agg);
            sprefix = 0;
        } else {
            atomicExch(&g_desc[bid], (FLAG_AGG << 32) | (unsigned long long)(unsigned)agg);
            int excl = 0;
            int j = bid - 1;
            while (true) {
                unsigned long long d = atomicAdd(&g_desc[j], 0ULL);
                unsigned long long flag = d >> 32;
                int val = (int)(unsigned)(d & 0xffffffffULL);
                if (flag == FLAG_PRE) { excl += val; break; }
                if (flag == FLAG_AGG) { excl += val; j--; }
            }
            atomicExch(&g_desc[bid],
                       (FLAG_PRE << 32) | (unsigned long long)(unsigned)(excl + agg));
            sprefix = excl;
        }
    }
    __syncthreads();

    if (i < m) {
        int v = sh[threadIdx.x] + sprefix;
        offs[i] = v;
        cur[i]  = v;
    }
}

// ---------------- kernel 3: scatter (pre-scales col to byte offset) ----------
__global__ void scatter_all_kernel(BuildArgs a, int* __restrict__ cur,
                                   int2* __restrict__ edges, int total,
                                   int n_users) {
    int i = blockIdx.x * blockDim.x + threadIdx.x;

    if (blockIdx.x == 0 && threadIdx.x < MAX_SCAN_BLOCKS)
        g_desc[threadIdx.x] = 0ULL;
    if (i == 0) g_scan_ctr = 0;

    if (i >= total) return;
    int k = 0;
    #pragma unroll
    for (int j = 1; j < 6; j++) if (i >= a.ebase[j]) k = j;
    int local = i - a.ebase[k];
    int r = __ldg(a.rows[k] + local);
    int p = atomicAdd(&cur[a.cbase[k] + r], 1);
    int colb = (k < 3) ? 0 : n_users;                 // item cols live after users
    int col  = __ldg(a.cols[k] + local);
    edges[p] = make_int2((colb + col) * (DIM * 2),    // byte offset into fp16 h
                         __float_as_int(__ldg(a.vals[k] + local)));
}

// ---------------- core gather loop: EXACT R11 configuration (frozen) ----------
// hp = h_base + lane*8 (loop-invariant). Per edge: 1 LDG.64 (edge, broadcast)
// + addr add + 1 LDG.64 (gather) + 4 cvt + 4 FFMA. No SHFL, no IMAD mul.
__device__ __forceinline__ float4 gather_row(const int* __restrict__ offs_row,
                                             const int2* __restrict__ edges,
                                             const char* __restrict__ hp) {
    int beg = __ldg(offs_row);
    int end = __ldg(offs_row + 1);
    float4 acc = make_float4(0.f, 0.f, 0.f, 0.f);
    #pragma unroll 4
    for (int e = beg; e < end; e++) {
        int2 ed = __ldg(edges + e);                       // warp-uniform broadcast
        float v = __int_as_float(ed.y);
        uint2 u = __ldg(reinterpret_cast<const uint2*>(hp + ed.x));
        float2 lo = __half22float2(*reinterpret_cast<__half2*>(&u.x));
        float2 hi = __half22float2(*reinterpret_cast<__half2*>(&u.y));
        acc.x += v * lo.x;
        acc.y += v * lo.y;
        acc.z += v * hi.x;
        acc.w += v * hi.y;
    }
    return acc;
}

// ---------------- fused CSR SpMM (intermediate stages, fp16 out) ----------------
__global__ void spmm_fused_kernel(const int* __restrict__ offs_u,
                                  const int* __restrict__ offs_i,
                                  const int2* __restrict__ edges,
                                  const __half* __restrict__ h,
                                  __half* __restrict__ out,
                                  int n_users, int n_total) {
    int w = (blockIdx.x * blockDim.x + threadIdx.x) >> 5;
    if (w >= n_total) return;
    int lane = threadIdx.x & 31;

    const int* orow = (w < n_users) ? (offs_u + w) : (offs_i + (w - n_users));
    const char* hp = reinterpret_cast<const char*>(h) + lane * 8;

    float4 acc = gather_row(orow, edges, hp);

    __half2 p0 = __floats2half2_rn(acc.x * STAGE_SCALE, acc.y * STAGE_SCALE);
    __half2 p1 = __floats2half2_rn(acc.z * STAGE_SCALE, acc.w * STAGE_SCALE);
    uint2 o;
    o.x = *reinterpret_cast<unsigned*>(&p0);
    o.y = *reinterpret_cast<unsigned*>(&p1);
    reinterpret_cast<uint2*>(out)[(size_t)w * (DIM / 4) + lane] = o;
}

// ---------------- final stage: SpMM + layer mean fused ----------------
// out = 0.25 * (emb + 64*H1 + 4096*H2 + 65536*acc)
__global__ void spmm_final_kernel(const int* __restrict__ offs_u,
                                  const int* __restrict__ offs_i,
                                  const int2* __restrict__ edges,
                                  const __half* __restrict__ h,
                                  const float* __restrict__ ue,
                                  const float* __restrict__ ie,
                                  const __half* __restrict__ h1,
                                  const __half* __restrict__ h2,
                                  float* __restrict__ out,
                                  int n_users, int n_total) {
    int w = (blockIdx.x * blockDim.x + threadIdx.x) >> 5;
    if (w >= n_total) return;
    int lane = threadIdx.x & 31;

    const int* orow;
    const float* emb;
    if (w < n_users) { orow = offs_u + w;             emb = ue + (size_t)w * DIM; }
    else             { orow = offs_i + (w - n_users); emb = ie + (size_t)(w - n_users) * DIM; }
    const char* hp = reinterpret_cast<const char*>(h) + lane * 8;

    float4 acc = gather_row(orow, edges, hp);

    size_t ri = (size_t)w * (DIM / 4) + lane;
    float4 a = __ldg(reinterpret_cast<const float4*>(emb) + lane);
    uint2 ub = __ldg(reinterpret_cast<const uint2*>(h1) + ri);
    uint2 uc = __ldg(reinterpret_cast<const uint2*>(h2) + ri);
    float2 b0 = __half22float2(*reinterpret_cast<__half2*>(&ub.x));
    float2 b1 = __half22float2(*reinterpret_cast<__half2*>(&ub.y));
    float2 c0 = __half22float2(*reinterpret_cast<__half2*>(&uc.x));
    float2 c1 = __half22float2(*reinterpret_cast<__half2*>(&uc.y));

    const float w1 = 64.0f, w2 = 4096.0f, w3 = 65536.0f;
    float4 o;
    o.x = 0.25f * (a.x + w1 * b0.x + w2 * c0.x + w3 * acc.x);
    o.y = 0.25f * (a.y + w1 * b0.y + w2 * c0.y + w3 * acc.y);
    o.z = 0.25f * (a.z + w1 * b1.x + w2 * c1.x + w3 * acc.z);
    o.w = 0.25f * (a.w + w1 * b1.y + w2 * c1.y + w3 * acc.w);
    reinterpret_cast<float4*>(out)[ri] = o;
}

static inline void launch_spmm(const int* offs_u, const int* offs_i, const int2* edges,
                               const __half* h, __half* out, int n_users, int n_total) {
    long long total = (long long)n_total * 32;
    int blocks = (int)((total + 255) / 256);
    spmm_fused_kernel<<<blocks, 256>>>(offs_u, offs_i, edges, h, out, n_users, n_total);
}

extern "C" void kernel_launch(void* const* d_in, const int* in_sizes, int n_in,
                              void* d_out, int out_size) {
    const float* user_emb = (const float*)d_in[0];
    const float* item_emb = (const float*)d_in[1];

    BuildArgs a;
    int mrows[6];
    int n_users = in_sizes[0] / DIM;
    int n_items = in_sizes[1] / DIM;
    mrows[0] = mrows[1] = mrows[2] = n_users;   // u1, u2, ucat
    mrows[3] = mrows[4] = mrows[5] = n_items;   // i1, i2, icat

    a.ebase[0] = 0;
    a.cbase[0] = 0;
    for (int k = 0; k < 6; k++) {
        a.rows[k] = (const int*)  d_in[2 + 3 * k];
        a.cols[k] = (const int*)  d_in[3 + 3 * k];
        a.vals[k] = (const float*)d_in[4 + 3 * k];
        a.ebase[k + 1] = a.ebase[k] + in_sizes[2 + 3 * k];
        a.cbase[k + 1] = a.cbase[k] + mrows[k] + 1;
    }
    int total_nnz = a.ebase[6];
    int L = a.cbase[6];
    int n_total = n_users + n_items;

    __half *E, *T, *S, *H1, *H2;
    cudaGetSymbolAddress((void**)&E,  g_E);
    cudaGetSymbolAddress((void**)&T,  g_T);
    cudaGetSymbolAddress((void**)&S,  g_S);
    cudaGetSymbolAddress((void**)&H1, g_H1);
    cudaGetSymbolAddress((void**)&H2, g_H2);

    int *counts, *offs, *cur; int2* edges;
    cudaGetSymbolAddress((void**)&counts, g_counts);
    cudaGetSymbolAddress((void**)&offs,   g_offs);
    cudaGetSymbolAddress((void**)&cur,    g_cur);
    cudaGetSymbolAddress((void**)&edges,  g_edges);

    size_t u4 = (size_t)n_users * (DIM / 4);
    size_t n4 = (size_t)n_total * (DIM / 4);

    // kernel 1: convert embeddings + histogram
    {
        size_t work = (size_t)total_nnz > n4 ? (size_t)total_nnz : n4;
        int blocks = (int)((work + 255) / 256);
        convhist_kernel<<<blocks, 256>>>(a, counts, user_emb, item_emb, E,
                                         u4, n4, total_nnz);
    }

    // kernel 2: single-pass scan (writes offs + cur, zeroes counts)
    {
        int nb = (L + SCAN_T - 1) / SCAN_T;
        scan_lookback_kernel<<<nb, SCAN_T>>>(counts, offs, cur, L);
    }

    // kernel 3: scatter into CSR edge slab (prescaled col byte offsets)
    scatter_all_kernel<<<(total_nnz + 255) / 256, 256>>>(a, cur, edges, total_nnz,
                                                         n_users);

    const int* O[6];
    for (int k = 0; k < 6; k++) O[k] = offs + a.cbase[k];

    // --- fused propagation: per layer, stage order m2, m1, mcat ---
    launch_spmm(O[1], O[4], edges, E, T,  n_users, n_total);
    launch_spmm(O[0], O[3], edges, T, S,  n_users, n_total);
    launch_spmm(O[2], O[5], edges, S, H1, n_users, n_total);

    launch_spmm(O[1], O[4], edges, H1, T, n_users, n_total);
    launch_spmm(O[0], O[3], edges, T,  S, n_users, n_total);
    launch_spmm(O[2], O[5], edges, S, H2, n_users, n_total);

    launch_spmm(O[1], O[4], edges, H2, T, n_users, n_total);
    launch_spmm(O[0], O[3], edges, T,  S, n_users, n_total);

    // final stage: SpMM(mcat, S) fused with the 4-layer mean -> d_out
    {
        long long total = (long long)n_total * 32;
        int blocks = (int)((total + 255) / 256);
        spmm_final_kernel<<<blocks, 256>>>(O[2], O[5], edges, S,
                                           user_emb, item_emb, H1, H2,
                                           (float*)d_out, n_users, n_total);
    }
}